// round 7
// baseline (speedup 1.0000x reference)
#include <cuda_runtime.h>
#include <cstdint>

// ============================================================================
// InstantNerf fused MLP, warp-level mma.sync tf32 (m16n8k8), sm_103.
// R7 == R6 (round 6 hit an infra failure; design untested, resubmitting).
//  - Warp tile = 64 rows x 32 cols (4 m16-tiles, half of N). B-fragments
//    amortized over 4 MMAs and split across warps -> ~40% fewer L1 bytes.
//  - CTA = 128 threads (4 warps = 2 m-groups x 2 n-halves), 128 rows.
//  - Two 64-col ping-pong activation buffers (stride 68, conflict-free),
//    ~70KB smem -> 3 CTAs/SM. Barrier between layers (cross-warp N split).
//  - Weights pre-fragmented to a __device__ global by a prep kernel (LDG).
// ============================================================================

static constexpr int THREADS = 128;
static constexpr int ROWS = 128;
static constexpr int HS = 68;    // buffer row stride (floats); 68%32=4 -> conflict-free

// smem float offsets
static constexpr int OFF_B1 = 0;      // 64
static constexpr int OFF_B2 = 64;     // 16
static constexpr int OFF_B3 = 80;     // 64
static constexpr int OFF_B4 = 144;    // 64
static constexpr int OFF_B5 = 208;    // 8 (padded)
static constexpr int OFF_H1 = 224;                    // 128*68 = 8704
static constexpr int OFF_H2 = OFF_H1 + ROWS * HS;     // 8928
static constexpr int SMEM_FLOATS = OFF_H2 + ROWS * HS; // 17632 -> 70528 B

// global fragment buffer (word offsets); slot s = k*NTtot + ntile
static constexpr int W1F = 0;       // 4k x 8n x 64 = 2048
static constexpr int W2F = 2048;    // 8k x 2n x 64 = 1024
static constexpr int W3F = 3072;    // 2048
static constexpr int W4F = 5120;    // 8k x 8n x 64 = 4096
static constexpr int W5F = 9216;    // 8k x 1n x 64 = 512
__device__ uint32_t g_wfrag[9728];

__device__ __forceinline__ uint32_t f2tf32(float x) {
    uint32_t u;
    asm("cvt.rna.tf32.f32 %0, %1;" : "=r"(u) : "f"(x));
    return u;
}

__device__ __forceinline__ void mma_tf32(float (&d)[4], uint32_t a0, uint32_t a1,
                                         uint32_t a2, uint32_t a3,
                                         uint32_t b0, uint32_t b1) {
    asm volatile(
        "mma.sync.aligned.m16n8k8.row.col.f32.tf32.tf32.f32 "
        "{%0,%1,%2,%3}, {%4,%5,%6,%7}, {%8,%9}, {%0,%1,%2,%3};"
        : "+f"(d[0]), "+f"(d[1]), "+f"(d[2]), "+f"(d[3])
        : "r"(a0), "r"(a1), "r"(a2), "r"(a3), "r"(b0), "r"(b1));
}

// ---------------- prep kernel: W[K][Nreal] -> B-fragment order ----------------
__device__ __forceinline__ void stage_section(uint32_t* dst, const float* W,
                                              int Nreal, int KT, int NT,
                                              int tid, int ntot) {
    int total = KT * NT * 64;
    for (int idx = tid; idx < total; idx += ntot) {
        int s = idx >> 6, rem = idx & 63;
        int lane = rem >> 1, half = rem & 1;
        int kstep = s / NT, nt = s - kstep * NT;
        int kk = kstep * 8 + (lane & 3) + half * 4;
        int nn = nt * 8 + (lane >> 2);
        float v = (nn < Nreal) ? W[kk * Nreal + nn] : 0.0f;
        dst[s * 64 + lane * 2 + half] = f2tf32(v);
    }
}

__global__ void prep_kernel(const float* __restrict__ W1, const float* __restrict__ W2,
                            const float* __restrict__ W3, const float* __restrict__ W4,
                            const float* __restrict__ W5) {
    int tid = blockIdx.x * blockDim.x + threadIdx.x;
    int ntot = gridDim.x * blockDim.x;
    stage_section(g_wfrag + W1F, W1, 64, 4, 8, tid, ntot);
    stage_section(g_wfrag + W2F, W2, 16, 8, 2, tid, ntot);
    stage_section(g_wfrag + W3F, W3, 64, 4, 8, tid, ntot);
    stage_section(g_wfrag + W4F, W4, 64, 8, 8, tid, ntot);
    stage_section(g_wfrag + W5F, W5, 3, 8, 1, tid, ntot);
}

// ---------------- layer core: 4 m-tiles x NT n-tiles from smem ----------------
template <int KT, int NT, int NTTOT>
__device__ __forceinline__ void run_layer(const uint32_t* __restrict__ sIn,
                                          const uint2* __restrict__ bfrag,
                                          const float* __restrict__ bias,
                                          int mrow0, int ntbase,
                                          int g, int tg, int lane,
                                          float (&acc)[4][NT][4]) {
#pragma unroll
    for (int m = 0; m < 4; m++)
#pragma unroll
        for (int nn = 0; nn < NT; nn++) {
            float2 bb = ((const float2*)bias)[(ntbase + nn) * 4 + tg];
            acc[m][nn][0] = bb.x; acc[m][nn][1] = bb.y;
            acc[m][nn][2] = bb.x; acc[m][nn][3] = bb.y;
        }
#pragma unroll
    for (int k = 0; k < KT; k++) {
        uint2 bf[NT];
#pragma unroll
        for (int nn = 0; nn < NT; nn++)
            bf[nn] = bfrag[(k * NTTOT + ntbase + nn) * 32 + lane];
#pragma unroll
        for (int m = 0; m < 4; m++) {
            const uint32_t* ap = sIn + (mrow0 + m * 16 + g) * HS + k * 8 + tg;
            uint32_t a0 = ap[0];
            uint32_t a1 = ap[8 * HS];
            uint32_t a2 = ap[4];
            uint32_t a3 = ap[8 * HS + 4];
#pragma unroll
            for (int nn = 0; nn < NT; nn++)
                mma_tf32(acc[m][nn], a0, a1, a2, a3, bf[nn].x, bf[nn].y);
        }
    }
}

// L1: A-fragments straight from gmem position [n,32]
__device__ __forceinline__ void run_layer1(const float* __restrict__ pos, int n,
                                           int rowbase, int ntbase,
                                           const uint2* __restrict__ bfrag,
                                           const float* __restrict__ bias,
                                           int g, int tg, int lane,
                                           float (&acc)[4][4][4]) {
#pragma unroll
    for (int m = 0; m < 4; m++)
#pragma unroll
        for (int nn = 0; nn < 4; nn++) {
            float2 bb = ((const float2*)bias)[(ntbase + nn) * 4 + tg];
            acc[m][nn][0] = bb.x; acc[m][nn][1] = bb.y;
            acc[m][nn][2] = bb.x; acc[m][nn][3] = bb.y;
        }
    const float* pr[8];
#pragma unroll
    for (int m = 0; m < 4; m++) {
        int ra = rowbase + m * 16 + g;      if (ra >= n) ra = n - 1;
        int rb = rowbase + m * 16 + 8 + g;  if (rb >= n) rb = n - 1;
        pr[2 * m]     = pos + (size_t)ra * 32 + tg;
        pr[2 * m + 1] = pos + (size_t)rb * 32 + tg;
    }
#pragma unroll
    for (int k = 0; k < 4; k++) {
        uint2 bf[4];
#pragma unroll
        for (int nn = 0; nn < 4; nn++)
            bf[nn] = bfrag[(k * 8 + ntbase + nn) * 32 + lane];
#pragma unroll
        for (int m = 0; m < 4; m++) {
            uint32_t a0 = f2tf32(pr[2 * m][k * 8]);
            uint32_t a1 = f2tf32(pr[2 * m + 1][k * 8]);
            uint32_t a2 = f2tf32(pr[2 * m][k * 8 + 4]);
            uint32_t a3 = f2tf32(pr[2 * m + 1][k * 8 + 4]);
#pragma unroll
            for (int nn = 0; nn < 4; nn++)
                mma_tf32(acc[m][nn], a0, a1, a2, a3, bf[nn].x, bf[nn].y);
        }
    }
}

// relu + tf32 + store to buffer at column base
template <int NT>
__device__ __forceinline__ void epi_relu_store(float (&acc)[4][NT][4],
                                               uint32_t* dst, int mrow0,
                                               int colbase, int g, int tg) {
#pragma unroll
    for (int m = 0; m < 4; m++)
#pragma unroll
        for (int nn = 0; nn < NT; nn++) {
            int r0 = mrow0 + m * 16 + g;
            uint2 lo, hi;
            lo.x = f2tf32(fmaxf(acc[m][nn][0], 0.0f));
            lo.y = f2tf32(fmaxf(acc[m][nn][1], 0.0f));
            hi.x = f2tf32(fmaxf(acc[m][nn][2], 0.0f));
            hi.y = f2tf32(fmaxf(acc[m][nn][3], 0.0f));
            *(uint2*)(dst + r0 * HS + colbase + nn * 8 + 2 * tg) = lo;
            *(uint2*)(dst + (r0 + 8) * HS + colbase + nn * 8 + 2 * tg) = hi;
        }
}

__global__ void __launch_bounds__(THREADS, 3)
nerf_mma_kernel(const float* __restrict__ position,
                const float* __restrict__ direction,
                const float* __restrict__ b1, const float* __restrict__ b2,
                const float* __restrict__ b3, const float* __restrict__ b4,
                const float* __restrict__ b5,
                float* __restrict__ out, int n) {
    extern __shared__ float smf[];
    uint32_t* smu = (uint32_t*)smf;

    const int tid = threadIdx.x;
    const int lane = tid & 31;
    const int wid = tid >> 5;          // 0..3
    const int g = lane >> 2;
    const int tg = lane & 3;
    const int mg = wid >> 1;           // m-group 0..1 (64 rows each)
    const int nh = wid & 1;            // n-half 0..1
    const int mrow0 = mg * 64;

    // biases
    if (tid < 64) smf[OFF_B1 + tid] = b1[tid];
    if (tid < 16) smf[OFF_B2 + tid] = b2[tid];
    if (tid < 64) smf[OFF_B3 + tid] = b3[tid];
    if (tid < 64) smf[OFF_B4 + tid] = b4[tid];
    if (tid < 8)  smf[OFF_B5 + tid] = (tid < 3) ? b5[tid] : 0.0f;

    const int base = blockIdx.x * ROWS;
    uint32_t* H1 = smu + OFF_H1;
    uint32_t* H2 = smu + OFF_H2;   // cols 0-15: density, 16-31: SH, later full 64

    // ---- SH(dir) -> H2 cols 16..31 (one row per thread) ----
    {
        int r = base + tid; if (r >= n) r = n - 1;
        const float* dp = direction + (size_t)r * 3;
        float x = dp[0], y = dp[1], z = dp[2];
        float xx = x * x, yy = y * y, zz = z * z;
        uint32_t* row = H2 + tid * HS + 16;
        row[0]  = f2tf32(0.28209479177387814f);
        row[1]  = f2tf32(0.4886025119029199f * y);
        row[2]  = f2tf32(0.4886025119029199f * z);
        row[3]  = f2tf32(0.4886025119029199f * x);
        row[4]  = f2tf32(1.0925484305920792f * x * y);
        row[5]  = f2tf32(1.0925484305920792f * y * z);
        row[6]  = f2tf32(0.9461746957575601f * zz - 0.31539156525252f);
        row[7]  = f2tf32(1.0925484305920792f * x * z);
        row[8]  = f2tf32(0.5462742152960396f * (xx - yy));
        row[9]  = f2tf32(0.5900435899266435f * y * (3.0f * xx - yy));
        row[10] = f2tf32(2.890611442640554f * x * y * z);
        row[11] = f2tf32(0.4570457994644658f * y * (5.0f * zz - 1.0f));
        row[12] = f2tf32(0.3731763325901154f * z * (5.0f * zz - 3.0f));
        row[13] = f2tf32(0.4570457994644658f * x * (5.0f * zz - 1.0f));
        row[14] = f2tf32(1.445305721320277f * z * (xx - yy));
        row[15] = f2tf32(0.5900435899266435f * x * (xx - 3.0f * yy));
    }
    __syncthreads();

    const uint2* fr = (const uint2*)g_wfrag;

    // ---- L1: pos @ W1 -> H1 cols [nh*32, +32) (relu) ----
    {
        float acc[4][4][4];
        run_layer1(position, n, base + mrow0, nh * 4, fr + (W1F >> 1),
                   smf + OFF_B1, g, tg, lane, acc);
        epi_relu_store<4>(acc, H1, mrow0, nh * 32, g, tg);
    }
    __syncthreads();

    // ---- L2: H1 @ W2 -> density tile nh (gmem + H2 cols nh*8) ----
    {
        float acc[4][1][4];
        run_layer<8, 1, 2>(H1, fr + (W2F >> 1), smf + OFF_B2, mrow0, nh,
                           g, tg, lane, acc);
#pragma unroll
        for (int m = 0; m < 4; m++) {
            int r0 = mrow0 + m * 16 + g;
            int gr0 = base + r0;
            float2 lo = make_float2(acc[m][0][0], acc[m][0][1]);
            float2 hi = make_float2(acc[m][0][2], acc[m][0][3]);
            if (gr0 < n)
                *(float2*)(out + (size_t)gr0 * 16 + nh * 8 + 2 * tg) = lo;
            if (gr0 + 8 < n)
                *(float2*)(out + (size_t)(gr0 + 8) * 16 + nh * 8 + 2 * tg) = hi;
            uint2 ulo, uhi;
            ulo.x = f2tf32(lo.x); ulo.y = f2tf32(lo.y);
            uhi.x = f2tf32(hi.x); uhi.y = f2tf32(hi.y);
            *(uint2*)(H2 + r0 * HS + nh * 8 + 2 * tg) = ulo;
            *(uint2*)(H2 + (r0 + 8) * HS + nh * 8 + 2 * tg) = uhi;
        }
    }
    __syncthreads();

    // ---- L3: H2 cols 0..31 (dens||SH) @ W3 -> H1 (relu) ----
    {
        float acc[4][4][4];
        run_layer<4, 4, 8>(H2, fr + (W3F >> 1), smf + OFF_B3, mrow0, nh * 4,
                           g, tg, lane, acc);
        epi_relu_store<4>(acc, H1, mrow0, nh * 32, g, tg);
    }
    __syncthreads();

    // ---- L4: H1 @ W4 -> H2 (relu) ----
    {
        float acc[4][4][4];
        run_layer<8, 4, 8>(H1, fr + (W4F >> 1), smf + OFF_B4, mrow0, nh * 4,
                           g, tg, lane, acc);
        epi_relu_store<4>(acc, H2, mrow0, nh * 32, g, tg);
    }
    __syncthreads();

    // ---- L5: H2 @ W5 -> color (sigmoid); n-half 0 warps only ----
    if (nh == 0) {
        float acc[4][1][4];
        run_layer<8, 1, 1>(H2, fr + (W5F >> 1), smf + OFF_B5, mrow0, 0,
                           g, tg, lane, acc);
        float* co = out + (size_t)n * 16;
#pragma unroll
        for (int m = 0; m < 4; m++) {
            int gr0 = base + mrow0 + m * 16 + g;
            float s0 = 1.0f / (1.0f + __expf(-acc[m][0][0]));
            float s1 = 1.0f / (1.0f + __expf(-acc[m][0][1]));
            float s2 = 1.0f / (1.0f + __expf(-acc[m][0][2]));
            float s3 = 1.0f / (1.0f + __expf(-acc[m][0][3]));
            if (tg == 0) {
                if (gr0 < n)     { co[(size_t)gr0 * 3 + 0] = s0;
                                   co[(size_t)gr0 * 3 + 1] = s1; }
                if (gr0 + 8 < n) { co[(size_t)(gr0 + 8) * 3 + 0] = s2;
                                   co[(size_t)(gr0 + 8) * 3 + 1] = s3; }
            } else if (tg == 1) {
                if (gr0 < n)     co[(size_t)gr0 * 3 + 2] = s0;
                if (gr0 + 8 < n) co[(size_t)(gr0 + 8) * 3 + 2] = s2;
            }
        }
    }
}

extern "C" void kernel_launch(void* const* d_in, const int* in_sizes, int n_in,
                              void* d_out, int out_size) {
    const float* position = (const float*)d_in[0];
    const float* direction = (const float*)d_in[1];
    const float* W1 = (const float*)d_in[2];
    const float* b1 = (const float*)d_in[3];
    const float* W2 = (const float*)d_in[4];
    const float* b2 = (const float*)d_in[5];
    const float* W3 = (const float*)d_in[6];
    const float* b3 = (const float*)d_in[7];
    const float* W4 = (const float*)d_in[8];
    const float* b4 = (const float*)d_in[9];
    const float* W5 = (const float*)d_in[10];
    const float* b5 = (const float*)d_in[11];
    float* out = (float*)d_out;

    int n = in_sizes[0] / 32;
    int ntiles = (n + ROWS - 1) / ROWS;
    if (ntiles <= 0) return;
    size_t smem_bytes = (size_t)SMEM_FLOATS * sizeof(float);

    cudaFuncSetAttribute(nerf_mma_kernel,
                         cudaFuncAttributeMaxDynamicSharedMemorySize,
                         (int)smem_bytes);
    prep_kernel<<<40, 256>>>(W1, W2, W3, W4, W5);
    nerf_mma_kernel<<<ntiles, THREADS, smem_bytes>>>(position, direction,
                                                     b1, b2, b3, b4, b5,
                                                     out, n);
}

// round 8
// speedup vs baseline: 2.2088x; 2.2088x over previous
#include <cuda_runtime.h>
#include <cstdint>

// ============================================================================
// InstantNerf fused MLP, warp-level mma.sync fp16 (m16n8k16, fp32 acc), sm_103.
// R8: R5's barrier-free structure + fp16 datapath (halves L1 bytes; fp16 has
// the same 10-bit mantissa as tf32, accumulation in fp32).
//  - CTA = 256 threads = 8 warps; each warp owns 32 samples, no barriers
//    after input staging.
//  - Weights pre-packed to f16x2 B-fragment order in __device__ global (LDG).
//  - Activations fp16 in smem: IN buffer (dens||SH, 32 cols, word-stride 20),
//    H buffer (64 cols, word-stride 36) — both provably conflict-free.
//  - 58 KB smem/CTA, launch_bounds(256,2) -> 16 warps/SM.
// ============================================================================

static constexpr int THREADS = 256;
static constexpr int ROWS = 256;
static constexpr int SW  = 36;   // H row stride (32-bit words = f16x2 units)
static constexpr int INW = 20;   // IN row stride (words)

// smem word offsets
static constexpr int OFF_B1 = 0;      // 64 f32
static constexpr int OFF_B2 = 64;     // 16
static constexpr int OFF_B3 = 80;     // 64
static constexpr int OFF_B4 = 144;    // 64
static constexpr int OFF_B5 = 208;    // 8 (padded)
static constexpr int OFF_IN = 224;                    // 256*20 = 5120
static constexpr int OFF_H  = OFF_IN + ROWS * INW;    // 5344
static constexpr int SMEM_WORDS = OFF_H + ROWS * SW;  // 14560 -> 58240 B

// global fragment buffer (word offsets); slot s = ks16*NTtot + ntile, 64 words
static constexpr int W1F = 0;       // 2k x 8n x 64 = 1024
static constexpr int W2F = 1024;    // 4k x 2n x 64 = 512
static constexpr int W3F = 1536;    // 1024
static constexpr int W4F = 2560;    // 4k x 8n x 64 = 2048
static constexpr int W5F = 4608;    // 4k x 1n x 64 = 256
__device__ uint32_t g_wfrag[4864];

// pack two fp32 -> f16x2 (lo = first arg)
__device__ __forceinline__ uint32_t h2pack(float lo, float hi) {
    uint32_t r;
    asm("cvt.rn.f16x2.f32 %0, %1, %2;" : "=r"(r) : "f"(hi), "f"(lo));
    return r;
}

__device__ __forceinline__ void mma_f16(float (&d)[4], uint32_t a0, uint32_t a1,
                                        uint32_t a2, uint32_t a3,
                                        uint32_t b0, uint32_t b1) {
    asm volatile(
        "mma.sync.aligned.m16n8k16.row.col.f32.f16.f16.f32 "
        "{%0,%1,%2,%3}, {%4,%5,%6,%7}, {%8,%9}, {%0,%1,%2,%3};"
        : "+f"(d[0]), "+f"(d[1]), "+f"(d[2]), "+f"(d[3])
        : "r"(a0), "r"(a1), "r"(a2), "r"(a3), "r"(b0), "r"(b1));
}

// ---------------- prep kernel: W[K][Nreal] -> f16x2 B-fragment order --------
// word w in slot s: lane = (w>>1), half = w&1 (b0/b1); g=lane>>2, tg=lane&3;
//   k0 = ks*16 + half*8 + 2*tg; nn = nt*8 + g; word = pack(W[k0][nn], W[k0+1][nn])
__device__ __forceinline__ void stage_section(uint32_t* dst, const float* W,
                                              int Nreal, int KT, int NT,
                                              int tid, int ntot) {
    int total = KT * NT * 64;
    for (int idx = tid; idx < total; idx += ntot) {
        int s = idx >> 6, rem = idx & 63;
        int lane = rem >> 1, half = rem & 1;
        int ks = s / NT, nt = s - ks * NT;
        int g = lane >> 2, tg = lane & 3;
        int k0 = ks * 16 + half * 8 + 2 * tg;
        int nn = nt * 8 + g;
        float v0 = (nn < Nreal) ? W[k0 * Nreal + nn] : 0.0f;
        float v1 = (nn < Nreal) ? W[(k0 + 1) * Nreal + nn] : 0.0f;
        dst[s * 64 + lane * 2 + half] = h2pack(v0, v1);
    }
}

__global__ void prep_kernel(const float* __restrict__ W1, const float* __restrict__ W2,
                            const float* __restrict__ W3, const float* __restrict__ W4,
                            const float* __restrict__ W5) {
    int tid = blockIdx.x * blockDim.x + threadIdx.x;
    int ntot = gridDim.x * blockDim.x;
    stage_section(g_wfrag + W1F, W1, 64, 2, 8, tid, ntot);
    stage_section(g_wfrag + W2F, W2, 16, 4, 2, tid, ntot);
    stage_section(g_wfrag + W3F, W3, 64, 2, 8, tid, ntot);
    stage_section(g_wfrag + W4F, W4, 64, 4, 8, tid, ntot);
    stage_section(g_wfrag + W5F, W5, 3, 4, 1, tid, ntot);
}

// ---------------- layer core (A fp16 in smem) ----------------
// KT = K/16 steps; A word addr: row*STRIDE + ks*8 + tg, a2 at +4.
template <int KT, int NT, int NTTOT, int STRIDE>
__device__ __forceinline__ void run_layer(const uint32_t* __restrict__ sIn,
                                          const uint2* __restrict__ bfrag,
                                          const float* __restrict__ bias,
                                          int mrow0, int g, int tg, int lane,
                                          float (&acc)[2][NT][4]) {
#pragma unroll
    for (int m = 0; m < 2; m++)
#pragma unroll
        for (int nn = 0; nn < NT; nn++) {
            float2 bb = ((const float2*)bias)[nn * 4 + tg];
            acc[m][nn][0] = bb.x; acc[m][nn][1] = bb.y;
            acc[m][nn][2] = bb.x; acc[m][nn][3] = bb.y;
        }
#pragma unroll
    for (int k = 0; k < KT; k++) {
        uint2 bf[NT];
#pragma unroll
        for (int nn = 0; nn < NT; nn++)
            bf[nn] = bfrag[(k * NTTOT + nn) * 32 + lane];
#pragma unroll
        for (int m = 0; m < 2; m++) {
            const uint32_t* ap = sIn + (mrow0 + m * 16 + g) * STRIDE + k * 8 + tg;
            uint32_t a0 = ap[0];
            uint32_t a1 = ap[8 * STRIDE];
            uint32_t a2 = ap[4];
            uint32_t a3 = ap[8 * STRIDE + 4];
#pragma unroll
            for (int nn = 0; nn < NT; nn++)
                mma_f16(acc[m][nn], a0, a1, a2, a3, bf[nn].x, bf[nn].y);
        }
    }
}

// L1: A from gmem position [n,32] fp32, converted inline (2 k16-steps)
__device__ __forceinline__ void run_layer1(const float* __restrict__ pos, int n,
                                           int rowbase,
                                           const uint2* __restrict__ bfrag,
                                           const float* __restrict__ bias,
                                           int g, int tg, int lane,
                                           float (&acc)[2][8][4]) {
#pragma unroll
    for (int m = 0; m < 2; m++)
#pragma unroll
        for (int nn = 0; nn < 8; nn++) {
            float2 bb = ((const float2*)bias)[nn * 4 + tg];
            acc[m][nn][0] = bb.x; acc[m][nn][1] = bb.y;
            acc[m][nn][2] = bb.x; acc[m][nn][3] = bb.y;
        }
    const float* pr[4];
#pragma unroll
    for (int m = 0; m < 2; m++) {
        int ra = rowbase + m * 16 + g;      if (ra >= n) ra = n - 1;
        int rb = rowbase + m * 16 + 8 + g;  if (rb >= n) rb = n - 1;
        pr[2 * m]     = pos + (size_t)ra * 32 + 2 * tg;
        pr[2 * m + 1] = pos + (size_t)rb * 32 + 2 * tg;
    }
#pragma unroll
    for (int k = 0; k < 2; k++) {
        uint2 bf[8];
#pragma unroll
        for (int nn = 0; nn < 8; nn++)
            bf[nn] = bfrag[(k * 8 + nn) * 32 + lane];
#pragma unroll
        for (int m = 0; m < 2; m++) {
            float2 va0 = *(const float2*)(pr[2 * m] + k * 16);
            float2 va1 = *(const float2*)(pr[2 * m + 1] + k * 16);
            float2 va2 = *(const float2*)(pr[2 * m] + k * 16 + 8);
            float2 va3 = *(const float2*)(pr[2 * m + 1] + k * 16 + 8);
            uint32_t a0 = h2pack(va0.x, va0.y);
            uint32_t a1 = h2pack(va1.x, va1.y);
            uint32_t a2 = h2pack(va2.x, va2.y);
            uint32_t a3 = h2pack(va3.x, va3.y);
#pragma unroll
            for (int nn = 0; nn < 8; nn++)
                mma_f16(acc[m][nn], a0, a1, a2, a3, bf[nn].x, bf[nn].y);
        }
    }
}

// relu + f16x2 pack + store
template <int NT, int STRIDE>
__device__ __forceinline__ void epi_relu_store(float (&acc)[2][NT][4],
                                               uint32_t* dst, int mrow0,
                                               int g, int tg) {
#pragma unroll
    for (int m = 0; m < 2; m++)
#pragma unroll
        for (int nn = 0; nn < NT; nn++) {
            int r0 = mrow0 + m * 16 + g;
            uint32_t lo = h2pack(fmaxf(acc[m][nn][0], 0.0f), fmaxf(acc[m][nn][1], 0.0f));
            uint32_t hi = h2pack(fmaxf(acc[m][nn][2], 0.0f), fmaxf(acc[m][nn][3], 0.0f));
            dst[r0 * STRIDE + nn * 4 + tg] = lo;
            dst[(r0 + 8) * STRIDE + nn * 4 + tg] = hi;
        }
}

__global__ void __launch_bounds__(THREADS, 2)
nerf_mma_kernel(const float* __restrict__ position,
                const float* __restrict__ direction,
                const float* __restrict__ b1, const float* __restrict__ b2,
                const float* __restrict__ b3, const float* __restrict__ b4,
                const float* __restrict__ b5,
                float* __restrict__ out, int n) {
    extern __shared__ float smf[];
    uint32_t* smu = (uint32_t*)smf;

    const int tid = threadIdx.x;
    const int lane = tid & 31;
    const int wid = tid >> 5;
    const int g = lane >> 2;
    const int tg = lane & 3;

    // biases (fp32)
    if (tid < 64) smf[OFF_B1 + tid] = b1[tid];
    if (tid < 16) smf[OFF_B2 + tid] = b2[tid];
    if (tid < 64) smf[OFF_B3 + tid] = b3[tid];
    if (tid < 64) smf[OFF_B4 + tid] = b4[tid];
    if (tid < 8)  smf[OFF_B5 + tid] = (tid < 3) ? b5[tid] : 0.0f;

    const int base = blockIdx.x * ROWS;
    uint32_t* IN = smu + OFF_IN;   // words 0-7 density, 8-15 SH (fp16 pairs)
    uint32_t* H  = smu + OFF_H;

    // ---- SH(dir) -> IN words 8..15 ----
    {
        int r = base + tid; if (r >= n) r = n - 1;
        const float* dp = direction + (size_t)r * 3;
        float x = dp[0], y = dp[1], z = dp[2];
        float xx = x * x, yy = y * y, zz = z * z;
        float sh[16];
        sh[0]  = 0.28209479177387814f;
        sh[1]  = 0.4886025119029199f * y;
        sh[2]  = 0.4886025119029199f * z;
        sh[3]  = 0.4886025119029199f * x;
        sh[4]  = 1.0925484305920792f * x * y;
        sh[5]  = 1.0925484305920792f * y * z;
        sh[6]  = 0.9461746957575601f * zz - 0.31539156525252f;
        sh[7]  = 1.0925484305920792f * x * z;
        sh[8]  = 0.5462742152960396f * (xx - yy);
        sh[9]  = 0.5900435899266435f * y * (3.0f * xx - yy);
        sh[10] = 2.890611442640554f * x * y * z;
        sh[11] = 0.4570457994644658f * y * (5.0f * zz - 1.0f);
        sh[12] = 0.3731763325901154f * z * (5.0f * zz - 3.0f);
        sh[13] = 0.4570457994644658f * x * (5.0f * zz - 1.0f);
        sh[14] = 1.445305721320277f * z * (xx - yy);
        sh[15] = 0.5900435899266435f * x * (xx - 3.0f * yy);
        uint32_t* row = IN + tid * INW + 8;
#pragma unroll
        for (int j = 0; j < 8; j++) row[j] = h2pack(sh[2 * j], sh[2 * j + 1]);
    }
    __syncthreads();
    // Each warp now works only on its own 32 rows: no more barriers.

    const int mrow0 = wid * 32;
    const uint2* fr = (const uint2*)g_wfrag;

    // ---- L1: pos @ W1 -> H (relu) ----
    {
        float acc[2][8][4];
        run_layer1(position, n, base + mrow0, fr + (W1F >> 1), smf + OFF_B1,
                   g, tg, lane, acc);
        epi_relu_store<8, SW>(acc, H, mrow0, g, tg);
    }
    __syncwarp();

    // ---- L2: H @ W2 -> density (gmem fp32) + IN words 0..7 ----
    {
        float acc[2][2][4];
        run_layer<4, 2, 2, SW>(H, fr + (W2F >> 1), smf + OFF_B2, mrow0,
                               g, tg, lane, acc);
#pragma unroll
        for (int m = 0; m < 2; m++)
#pragma unroll
            for (int nn = 0; nn < 2; nn++) {
                int r0 = mrow0 + m * 16 + g;
                int gr0 = base + r0;
                float2 lo = make_float2(acc[m][nn][0], acc[m][nn][1]);
                float2 hi = make_float2(acc[m][nn][2], acc[m][nn][3]);
                if (gr0 < n)
                    *(float2*)(out + (size_t)gr0 * 16 + nn * 8 + 2 * tg) = lo;
                if (gr0 + 8 < n)
                    *(float2*)(out + (size_t)(gr0 + 8) * 16 + nn * 8 + 2 * tg) = hi;
                IN[r0 * INW + nn * 4 + tg] = h2pack(lo.x, lo.y);
                IN[(r0 + 8) * INW + nn * 4 + tg] = h2pack(hi.x, hi.y);
            }
    }
    __syncwarp();

    // ---- L3: IN (dens||SH) @ W3 -> H (relu) ----
    {
        float acc[2][8][4];
        run_layer<2, 8, 8, INW>(IN, fr + (W3F >> 1), smf + OFF_B3, mrow0,
                                g, tg, lane, acc);
        epi_relu_store<8, SW>(acc, H, mrow0, g, tg);
    }
    __syncwarp();

    // ---- L4: H @ W4 -> H in place (safe: warp reads all before writing) ----
    {
        float acc[2][8][4];
        run_layer<4, 8, 8, SW>(H, fr + (W4F >> 1), smf + OFF_B4, mrow0,
                               g, tg, lane, acc);
        epi_relu_store<8, SW>(acc, H, mrow0, g, tg);
    }
    __syncwarp();

    // ---- L5: H @ W5 -> color (sigmoid) ----
    {
        float acc[2][1][4];
        run_layer<4, 1, 1, SW>(H, fr + (W5F >> 1), smf + OFF_B5, mrow0,
                               g, tg, lane, acc);
        float* co = out + (size_t)n * 16;
#pragma unroll
        for (int m = 0; m < 2; m++) {
            int gr0 = base + mrow0 + m * 16 + g;
            float s0 = 1.0f / (1.0f + __expf(-acc[m][0][0]));
            float s1 = 1.0f / (1.0f + __expf(-acc[m][0][1]));
            float s2 = 1.0f / (1.0f + __expf(-acc[m][0][2]));
            float s3 = 1.0f / (1.0f + __expf(-acc[m][0][3]));
            if (tg == 0) {
                if (gr0 < n)     { co[(size_t)gr0 * 3 + 0] = s0;
                                   co[(size_t)gr0 * 3 + 1] = s1; }
                if (gr0 + 8 < n) { co[(size_t)(gr0 + 8) * 3 + 0] = s2;
                                   co[(size_t)(gr0 + 8) * 3 + 1] = s3; }
            } else if (tg == 1) {
                if (gr0 < n)     co[(size_t)gr0 * 3 + 2] = s0;
                if (gr0 + 8 < n) co[(size_t)(gr0 + 8) * 3 + 2] = s2;
            }
        }
    }
}

extern "C" void kernel_launch(void* const* d_in, const int* in_sizes, int n_in,
                              void* d_out, int out_size) {
    const float* position = (const float*)d_in[0];
    const float* direction = (const float*)d_in[1];
    const float* W1 = (const float*)d_in[2];
    const float* b1 = (const float*)d_in[3];
    const float* W2 = (const float*)d_in[4];
    const float* b2 = (const float*)d_in[5];
    const float* W3 = (const float*)d_in[6];
    const float* b3 = (const float*)d_in[7];
    const float* W4 = (const float*)d_in[8];
    const float* b4 = (const float*)d_in[9];
    const float* W5 = (const float*)d_in[10];
    const float* b5 = (const float*)d_in[11];
    float* out = (float*)d_out;

    int n = in_sizes[0] / 32;
    int ntiles = (n + ROWS - 1) / ROWS;
    if (ntiles <= 0) return;
    size_t smem_bytes = (size_t)SMEM_WORDS * 4;

    cudaFuncSetAttribute(nerf_mma_kernel,
                         cudaFuncAttributeMaxDynamicSharedMemorySize,
                         (int)smem_bytes);
    prep_kernel<<<20, 256>>>(W1, W2, W3, W4, W5);
    nerf_mma_kernel<<<ntiles, THREADS, smem_bytes>>>(position, direction,
                                                     b1, b2, b3, b4, b5,
                                                     out, n);
}